// round 2
// baseline (speedup 1.0000x reference)
#include <cuda_runtime.h>
#include <cuda_bf16.h>
#include <cstdint>

#define N_NODES 2048
#define EPS 0.01f
#define ROWS_PER_BLOCK 16
#define THREADS 256
#define NBLOCKS_X (N_NODES / ROWS_PER_BLOCK)   // 128
#define MAX_BLOCKS 4096

__device__ int g_partials[MAX_BLOCKS];
__device__ unsigned int g_arrive = 0;

__global__ void __launch_bounds__(THREADS) count_kernel(
    const float* __restrict__ W, const float* __restrict__ pred,
    float* __restrict__ out, int nblocks)
{
    const int b = blockIdx.y;
    const int row0 = blockIdx.x * ROWS_PER_BLOCK;
    const int bid = blockIdx.y * gridDim.x + blockIdx.x;

    __shared__ float4 s_pred[N_NODES / 4];

    // cache pred[b] in shared (8 KB)
    const float4* predb = (const float4*)(pred + (size_t)b * N_NODES);
    for (int i = threadIdx.x; i < N_NODES / 4; i += THREADS)
        s_pred[i] = predb[i];
    __syncthreads();

    // channel 1 of W for this batch: W[b,1,:,:]
    const float4* Wb = (const float4*)(W + ((size_t)b * 2 + 1) * (size_t)N_NODES * N_NODES);

    int cnt = 0;
    for (int r = 0; r < ROWS_PER_BLOCK; ++r) {
        const int row = row0 + r;
        const float pi = ((const float*)s_pred)[row];
        const float4* wrow = Wb + (size_t)row * (N_NODES / 4);
        #pragma unroll 8
        for (int c = threadIdx.x; c < N_NODES / 4; c += THREADS) {
            const float4 w  = wrow[c];
            const float4 pj = s_pred[c];
            cnt += (w.x == 1.0f) & (fabsf(pi - pj.x) < EPS);
            cnt += (w.y == 1.0f) & (fabsf(pi - pj.y) < EPS);
            cnt += (w.z == 1.0f) & (fabsf(pi - pj.z) < EPS);
            cnt += (w.w == 1.0f) & (fabsf(pi - pj.w) < EPS);
        }
    }

    // block reduce
    #pragma unroll
    for (int o = 16; o > 0; o >>= 1)
        cnt += __shfl_xor_sync(0xffffffffu, cnt, o);

    __shared__ int warpsum[THREADS / 32];
    if ((threadIdx.x & 31) == 0)
        warpsum[threadIdx.x >> 5] = cnt;
    __syncthreads();

    __shared__ bool s_last;
    if (threadIdx.x == 0) {
        int v = 0;
        #pragma unroll
        for (int i = 0; i < THREADS / 32; ++i)
            v += warpsum[i];
        g_partials[bid] = v;
        __threadfence();
        unsigned int old = atomicAdd(&g_arrive, 1u);
        s_last = (old == (unsigned)(nblocks - 1));
    }
    __syncthreads();

    // last block to arrive does the final reduction
    if (s_last) {
        int v = 0;
        for (int i = threadIdx.x; i < nblocks; i += THREADS)
            v += g_partials[i];
        #pragma unroll
        for (int o = 16; o > 0; o >>= 1)
            v += __shfl_xor_sync(0xffffffffu, v, o);
        if ((threadIdx.x & 31) == 0)
            warpsum[threadIdx.x >> 5] = v;
        __syncthreads();
        if (threadIdx.x == 0) {
            int t = 0;
            #pragma unroll
            for (int i = 0; i < THREADS / 32; ++i)
                t += warpsum[i];
            out[0] = (float)t;
            g_arrive = 0;  // reset for next graph replay (deterministic)
        }
    }
}

extern "C" void kernel_launch(void* const* d_in, const int* in_sizes, int n_in,
                              void* d_out, int out_size)
{
    const float* W    = (const float*)d_in[0];
    const float* pred = (const float*)d_in[1];
    float* out = (float*)d_out;

    const int B = in_sizes[1] / N_NODES;  // pred has B*N elements
    dim3 grid(NBLOCKS_X, B);
    count_kernel<<<grid, THREADS>>>(W, pred, out, NBLOCKS_X * B);
}

// round 3
// speedup vs baseline: 1.1220x; 1.1220x over previous
#include <cuda_runtime.h>
#include <cuda_bf16.h>
#include <cstdint>

#define N_NODES 2048
#define EPS 0.01f
#define ROWS_PER_BLOCK 16
#define ROW_UNROLL 4
#define THREADS 256
#define NBLOCKS_X (N_NODES / ROWS_PER_BLOCK)   // 128
#define MAX_BLOCKS 4096

__device__ int g_partials[MAX_BLOCKS];
__device__ unsigned int g_arrive = 0;

__device__ __forceinline__ int pair4(const float4 w, const float pi, const float4 pj)
{
    int c = 0;
    c += (w.x == 1.0f) & (fabsf(pi - pj.x) < EPS);
    c += (w.y == 1.0f) & (fabsf(pi - pj.y) < EPS);
    c += (w.z == 1.0f) & (fabsf(pi - pj.z) < EPS);
    c += (w.w == 1.0f) & (fabsf(pi - pj.w) < EPS);
    return c;
}

__global__ void __launch_bounds__(THREADS) count_kernel(
    const float* __restrict__ W, const float* __restrict__ pred,
    float* __restrict__ out, int nblocks)
{
    const int b = blockIdx.y;
    const int row0 = blockIdx.x * ROWS_PER_BLOCK;
    const int bid = blockIdx.y * gridDim.x + blockIdx.x;
    const int tid = threadIdx.x;

    __shared__ float4 s_pred[N_NODES / 4];

    // cache pred[b] in shared (8 KB)
    const float4* predb = (const float4*)(pred + (size_t)b * N_NODES);
    for (int i = tid; i < N_NODES / 4; i += THREADS)
        s_pred[i] = predb[i];
    __syncthreads();

    // This thread's two fixed column groups (same for every row) — hoist to regs.
    const float4 pj0 = s_pred[tid];
    const float4 pj1 = s_pred[tid + THREADS];
    const float* s_f = (const float*)s_pred;

    // channel 1 of W for this batch: W[b,1,:,:]
    const float4* Wb = (const float4*)(W + ((size_t)b * 2 + 1) * (size_t)N_NODES * N_NODES);

    int cnt = 0;
    #pragma unroll
    for (int r0 = 0; r0 < ROWS_PER_BLOCK; r0 += ROW_UNROLL) {
        // front-batch 8 independent 128-bit streaming loads
        float4 w[ROW_UNROLL][2];
        #pragma unroll
        for (int k = 0; k < ROW_UNROLL; ++k) {
            const float4* wrow = Wb + (size_t)(row0 + r0 + k) * (N_NODES / 4);
            w[k][0] = __ldcs(wrow + tid);
            w[k][1] = __ldcs(wrow + tid + THREADS);
        }
        #pragma unroll
        for (int k = 0; k < ROW_UNROLL; ++k) {
            const float pi = s_f[row0 + r0 + k];
            cnt += pair4(w[k][0], pi, pj0);
            cnt += pair4(w[k][1], pi, pj1);
        }
    }

    // block reduce
    #pragma unroll
    for (int o = 16; o > 0; o >>= 1)
        cnt += __shfl_xor_sync(0xffffffffu, cnt, o);

    __shared__ int warpsum[THREADS / 32];
    if ((tid & 31) == 0)
        warpsum[tid >> 5] = cnt;
    __syncthreads();

    __shared__ bool s_last;
    if (tid == 0) {
        int v = 0;
        #pragma unroll
        for (int i = 0; i < THREADS / 32; ++i)
            v += warpsum[i];
        g_partials[bid] = v;
        __threadfence();
        unsigned int old = atomicAdd(&g_arrive, 1u);
        s_last = (old == (unsigned)(nblocks - 1));
    }
    __syncthreads();

    // last block to arrive does the final reduction
    if (s_last) {
        int v = 0;
        for (int i = tid; i < nblocks; i += THREADS)
            v += g_partials[i];
        #pragma unroll
        for (int o = 16; o > 0; o >>= 1)
            v += __shfl_xor_sync(0xffffffffu, v, o);
        if ((tid & 31) == 0)
            warpsum[tid >> 5] = v;
        __syncthreads();
        if (tid == 0) {
            int t = 0;
            #pragma unroll
            for (int i = 0; i < THREADS / 32; ++i)
                t += warpsum[i];
            out[0] = (float)t;
            g_arrive = 0;  // reset for next graph replay (deterministic)
        }
    }
}

extern "C" void kernel_launch(void* const* d_in, const int* in_sizes, int n_in,
                              void* d_out, int out_size)
{
    const float* W    = (const float*)d_in[0];
    const float* pred = (const float*)d_in[1];
    float* out = (float*)d_out;

    const int B = in_sizes[1] / N_NODES;  // pred has B*N elements
    dim3 grid(NBLOCKS_X, B);
    count_kernel<<<grid, THREADS>>>(W, pred, out, NBLOCKS_X * B);
}

// round 4
// speedup vs baseline: 1.2418x; 1.1069x over previous
#include <cuda_runtime.h>
#include <cuda_bf16.h>
#include <cstdint>

#define N_NODES 2048
#define EPS 0.01f
#define ROWS_PER_BLOCK 8
#define ROW_UNROLL 4
#define THREADS 256
#define NBLOCKS_X (N_NODES / ROWS_PER_BLOCK)   // 256
#define MAX_BLOCKS 4096

__device__ int g_partials[MAX_BLOCKS];
__device__ unsigned int g_arrive = 0;

__device__ __forceinline__ int pair4(const float4 w, const float pi, const float4 pj)
{
    int c = 0;
    c += (w.x == 1.0f) & (fabsf(pi - pj.x) < EPS);
    c += (w.y == 1.0f) & (fabsf(pi - pj.y) < EPS);
    c += (w.z == 1.0f) & (fabsf(pi - pj.z) < EPS);
    c += (w.w == 1.0f) & (fabsf(pi - pj.w) < EPS);
    return c;
}

__global__ void __launch_bounds__(THREADS, 4) count_kernel(
    const float* __restrict__ W, const float* __restrict__ pred,
    float* __restrict__ out, int nblocks)
{
    const int b = blockIdx.y;
    const int row0 = blockIdx.x * ROWS_PER_BLOCK;
    const int bid = blockIdx.y * gridDim.x + blockIdx.x;
    const int tid = threadIdx.x;

    __shared__ float4 s_pred[N_NODES / 4];

    // cache pred[b] in shared (8 KB)
    const float4* predb = (const float4*)(pred + (size_t)b * N_NODES);
    for (int i = tid; i < N_NODES / 4; i += THREADS)
        s_pred[i] = predb[i];
    __syncthreads();

    // This thread's two fixed column groups (same for every row) — keep in regs.
    const float4 pj0 = s_pred[tid];
    const float4 pj1 = s_pred[tid + THREADS];
    const float* s_f = (const float*)s_pred;

    // channel 1 of W for this batch: W[b,1,:,:]
    const float4* Wb = (const float4*)(W + ((size_t)b * 2 + 1) * (size_t)N_NODES * N_NODES);

    int cnt = 0;
    #pragma unroll
    for (int r0 = 0; r0 < ROWS_PER_BLOCK; r0 += ROW_UNROLL) {
        // front-batch 8 independent 128-bit streaming loads (needs ~32 live regs)
        float4 w[ROW_UNROLL][2];
        #pragma unroll
        for (int k = 0; k < ROW_UNROLL; ++k) {
            const float4* wrow = Wb + (size_t)(row0 + r0 + k) * (N_NODES / 4);
            w[k][0] = __ldcs(wrow + tid);
            w[k][1] = __ldcs(wrow + tid + THREADS);
        }
        #pragma unroll
        for (int k = 0; k < ROW_UNROLL; ++k) {
            const float pi = s_f[row0 + r0 + k];
            cnt += pair4(w[k][0], pi, pj0);
            cnt += pair4(w[k][1], pi, pj1);
        }
    }

    // block reduce
    #pragma unroll
    for (int o = 16; o > 0; o >>= 1)
        cnt += __shfl_xor_sync(0xffffffffu, cnt, o);

    __shared__ int warpsum[THREADS / 32];
    if ((tid & 31) == 0)
        warpsum[tid >> 5] = cnt;
    __syncthreads();

    __shared__ bool s_last;
    if (tid == 0) {
        int v = 0;
        #pragma unroll
        for (int i = 0; i < THREADS / 32; ++i)
            v += warpsum[i];
        g_partials[bid] = v;
        __threadfence();
        unsigned int old = atomicAdd(&g_arrive, 1u);
        s_last = (old == (unsigned)(nblocks - 1));
    }
    __syncthreads();

    // last block to arrive does the final reduction
    if (s_last) {
        int v = 0;
        for (int i = tid; i < nblocks; i += THREADS)
            v += g_partials[i];
        #pragma unroll
        for (int o = 16; o > 0; o >>= 1)
            v += __shfl_xor_sync(0xffffffffu, v, o);
        if ((tid & 31) == 0)
            warpsum[tid >> 5] = v;
        __syncthreads();
        if (tid == 0) {
            int t = 0;
            #pragma unroll
            for (int i = 0; i < THREADS / 32; ++i)
                t += warpsum[i];
            out[0] = (float)t;
            g_arrive = 0;  // reset for next graph replay (deterministic)
        }
    }
}

extern "C" void kernel_launch(void* const* d_in, const int* in_sizes, int n_in,
                              void* d_out, int out_size)
{
    const float* W    = (const float*)d_in[0];
    const float* pred = (const float*)d_in[1];
    float* out = (float*)d_out;

    const int B = in_sizes[1] / N_NODES;  // pred has B*N elements
    dim3 grid(NBLOCKS_X, B);
    count_kernel<<<grid, THREADS>>>(W, pred, out, NBLOCKS_X * B);
}

// round 5
// speedup vs baseline: 1.2912x; 1.0398x over previous
#include <cuda_runtime.h>
#include <cuda_bf16.h>
#include <cstdint>

#define N_NODES 2048
#define EPS 0.01f
#define ROWS_PER_BLOCK 16
#define RU 2                               // rows per pipeline stage
#define STAGES (ROWS_PER_BLOCK / RU)       // 8
#define THREADS 256
#define NBLOCKS_X (N_NODES / ROWS_PER_BLOCK)   // 128
#define MAX_BLOCKS 4096

__device__ int g_partials[MAX_BLOCKS];
__device__ unsigned int g_arrive = 0;

__device__ __forceinline__ int pair4(const float4 w, const float pi, const float4 pj)
{
    int c = 0;
    c += (w.x == 1.0f) & (fabsf(pi - pj.x) < EPS);
    c += (w.y == 1.0f) & (fabsf(pi - pj.y) < EPS);
    c += (w.z == 1.0f) & (fabsf(pi - pj.z) < EPS);
    c += (w.w == 1.0f) & (fabsf(pi - pj.w) < EPS);
    return c;
}

__global__ void __launch_bounds__(THREADS, 4) count_kernel(
    const float* __restrict__ W, const float* __restrict__ pred,
    float* __restrict__ out, int nblocks)
{
    const int b = blockIdx.y;
    const int row0 = blockIdx.x * ROWS_PER_BLOCK;
    const int bid = blockIdx.y * gridDim.x + blockIdx.x;
    const int tid = threadIdx.x;

    __shared__ float4 s_pred[N_NODES / 4];

    const float4* predb = (const float4*)(pred + (size_t)b * N_NODES);
    for (int i = tid; i < N_NODES / 4; i += THREADS)
        s_pred[i] = predb[i];
    __syncthreads();

    // Fixed per-thread column groups (same for every row) — registers.
    const float4 pj0 = s_pred[tid];
    const float4 pj1 = s_pred[tid + THREADS];
    const float* s_f = (const float*)s_pred;

    // channel 1 of W for this batch: W[b,1,:,:]; this thread's column base
    const float4* Wt = (const float4*)(W + ((size_t)b * 2 + 1) * (size_t)N_NODES * N_NODES)
                       + (size_t)row0 * (N_NODES / 4) + tid;

    // Software pipeline: double-buffered register stages (RU rows x 2 cols each)
    float4 w[2][RU][2];

    // prologue: load stage 0
    #pragma unroll
    for (int k = 0; k < RU; ++k) {
        const float4* p = Wt + (size_t)k * (N_NODES / 4);
        w[0][k][0] = __ldcs(p);
        w[0][k][1] = __ldcs(p + THREADS);
    }

    int cnt = 0;
    #pragma unroll
    for (int s = 1; s < STAGES; ++s) {
        const int cur = (s - 1) & 1, nxt = s & 1;
        // issue next stage's loads first
        #pragma unroll
        for (int k = 0; k < RU; ++k) {
            const float4* p = Wt + (size_t)(s * RU + k) * (N_NODES / 4);
            w[nxt][k][0] = __ldcs(p);
            w[nxt][k][1] = __ldcs(p + THREADS);
        }
        // consume current stage while next loads are in flight
        #pragma unroll
        for (int k = 0; k < RU; ++k) {
            const float pi = s_f[row0 + (s - 1) * RU + k];
            cnt += pair4(w[cur][k][0], pi, pj0);
            cnt += pair4(w[cur][k][1], pi, pj1);
        }
    }
    // epilogue: consume last stage
    #pragma unroll
    for (int k = 0; k < RU; ++k) {
        const float pi = s_f[row0 + (STAGES - 1) * RU + k];
        cnt += pair4(w[(STAGES - 1) & 1][k][0], pi, pj0);
        cnt += pair4(w[(STAGES - 1) & 1][k][1], pi, pj1);
    }

    // block reduce
    #pragma unroll
    for (int o = 16; o > 0; o >>= 1)
        cnt += __shfl_xor_sync(0xffffffffu, cnt, o);

    __shared__ int warpsum[THREADS / 32];
    if ((tid & 31) == 0)
        warpsum[tid >> 5] = cnt;
    __syncthreads();

    __shared__ bool s_last;
    if (tid == 0) {
        int v = 0;
        #pragma unroll
        for (int i = 0; i < THREADS / 32; ++i)
            v += warpsum[i];
        g_partials[bid] = v;
        __threadfence();
        unsigned int old = atomicAdd(&g_arrive, 1u);
        s_last = (old == (unsigned)(nblocks - 1));
    }
    __syncthreads();

    if (s_last) {
        int v = 0;
        for (int i = tid; i < nblocks; i += THREADS)
            v += g_partials[i];
        #pragma unroll
        for (int o = 16; o > 0; o >>= 1)
            v += __shfl_xor_sync(0xffffffffu, v, o);
        if ((tid & 31) == 0)
            warpsum[tid >> 5] = v;
        __syncthreads();
        if (tid == 0) {
            int t = 0;
            #pragma unroll
            for (int i = 0; i < THREADS / 32; ++i)
                t += warpsum[i];
            out[0] = (float)t;
            g_arrive = 0;  // reset for next graph replay
        }
    }
}

extern "C" void kernel_launch(void* const* d_in, const int* in_sizes, int n_in,
                              void* d_out, int out_size)
{
    const float* W    = (const float*)d_in[0];
    const float* pred = (const float*)d_in[1];
    float* out = (float*)d_out;

    const int B = in_sizes[1] / N_NODES;
    dim3 grid(NBLOCKS_X, B);
    count_kernel<<<grid, THREADS>>>(W, pred, out, NBLOCKS_X * B);
}

// round 6
// speedup vs baseline: 1.3019x; 1.0083x over previous
#include <cuda_runtime.h>
#include <cuda_bf16.h>
#include <cstdint>

#define N_NODES 2048
#define NQ (N_NODES / 4)          // 512 float4 per row
#define EPS 0.01f
#define THREADS 256
#define CTAS_PER_SM 4
#define NUM_SMS 148
#define NCTAS (NUM_SMS * CTAS_PER_SM)   // 592
#define MAX_BLOCKS 4096

__device__ int g_partials[MAX_BLOCKS];
__device__ unsigned int g_arrive = 0;

__device__ __forceinline__ int pair4(const float4 w, const float pi, const float4 pj)
{
    int c = 0;
    c += (w.x == 1.0f) & (fabsf(pi - pj.x) < EPS);
    c += (w.y == 1.0f) & (fabsf(pi - pj.y) < EPS);
    c += (w.z == 1.0f) & (fabsf(pi - pj.z) < EPS);
    c += (w.w == 1.0f) & (fabsf(pi - pj.w) < EPS);
    return c;
}

__global__ void __launch_bounds__(THREADS, CTAS_PER_SM) count_kernel(
    const float* __restrict__ W, const float* __restrict__ pred,
    float* __restrict__ out, int totalRows, int nblocks)
{
    const int bid = blockIdx.x;
    const int tid = threadIdx.x;

    // Even partition of global rows: max imbalance 1 row (~3.7%)
    const int start = (int)(((long long)bid * totalRows) / nblocks);
    const int end   = (int)(((long long)(bid + 1) * totalRows) / nblocks);

    int cnt = 0;
    if (start < end) {
        // --- prologue: state for row `start` ---
        int b  = start >> 11;
        int ri = start & (N_NODES - 1);
        const float* predb = pred + ((size_t)b << 11);
        // per-thread fixed column groups for this batch (registers, L2-hot loads)
        float4 pj0 = __ldg((const float4*)predb + tid);
        float4 pj1 = __ldg((const float4*)predb + tid + THREADS);
        int curb = b;

        const float4* wrow = (const float4*)(W + ((size_t)(2 * b + 1)) * (size_t)N_NODES * N_NODES)
                             + (size_t)ri * NQ;
        float4 w0[2], w1[2];
        float  pi[2];
        w0[0] = __ldcs(wrow + tid);
        w1[0] = __ldcs(wrow + tid + THREADS);
        pi[0] = __ldg(predb + ri);

        int p = 0;
        for (int r = start; r < end; ++r) {
            const int nxt = p ^ 1;
            const int rn = r + 1;
            if (rn < end) {
                const int bn  = rn >> 11;
                const int rin = rn & (N_NODES - 1);
                const float4* wn = (const float4*)(W + ((size_t)(2 * bn + 1)) * (size_t)N_NODES * N_NODES)
                                   + (size_t)rin * NQ;
                w0[nxt] = __ldcs(wn + tid);
                w1[nxt] = __ldcs(wn + tid + THREADS);
                pi[nxt] = __ldg(pred + ((size_t)bn << 11) + rin);
            }
            // refresh pj registers on (rare) batch transition
            const int rb = r >> 11;
            if (rb != curb) {
                curb = rb;
                const float* pb = pred + ((size_t)rb << 11);
                pj0 = __ldg((const float4*)pb + tid);
                pj1 = __ldg((const float4*)pb + tid + THREADS);
            }
            cnt += pair4(w0[p], pi[p], pj0);
            cnt += pair4(w1[p], pi[p], pj1);
            p = nxt;
        }
    }

    // block reduce
    #pragma unroll
    for (int o = 16; o > 0; o >>= 1)
        cnt += __shfl_xor_sync(0xffffffffu, cnt, o);

    __shared__ int warpsum[THREADS / 32];
    if ((tid & 31) == 0)
        warpsum[tid >> 5] = cnt;
    __syncthreads();

    __shared__ bool s_last;
    if (tid == 0) {
        int v = 0;
        #pragma unroll
        for (int i = 0; i < THREADS / 32; ++i)
            v += warpsum[i];
        g_partials[bid] = v;
        __threadfence();
        unsigned int old = atomicAdd(&g_arrive, 1u);
        s_last = (old == (unsigned)(nblocks - 1));
    }
    __syncthreads();

    // last block finalizes
    if (s_last) {
        int v = 0;
        for (int i = tid; i < nblocks; i += THREADS)
            v += g_partials[i];
        #pragma unroll
        for (int o = 16; o > 0; o >>= 1)
            v += __shfl_xor_sync(0xffffffffu, v, o);
        if ((tid & 31) == 0)
            warpsum[tid >> 5] = v;
        __syncthreads();
        if (tid == 0) {
            int t = 0;
            #pragma unroll
            for (int i = 0; i < THREADS / 32; ++i)
                t += warpsum[i];
            out[0] = (float)t;
            g_arrive = 0;  // reset for next graph replay
        }
    }
}

extern "C" void kernel_launch(void* const* d_in, const int* in_sizes, int n_in,
                              void* d_out, int out_size)
{
    const float* W    = (const float*)d_in[0];
    const float* pred = (const float*)d_in[1];
    float* out = (float*)d_out;

    const int B = in_sizes[1] / N_NODES;
    const int totalRows = B * N_NODES;      // 16384
    count_kernel<<<NCTAS, THREADS>>>(W, pred, out, totalRows, NCTAS);
}